// round 5
// baseline (speedup 1.0000x reference)
#include <cuda_runtime.h>

#define NN 100000
#define NE 1280000
#define D 64
#define NN4 (NN / 4)        // 25000
#define AGG4 (NN * D / 4)   // 1600000

// ---- scratch: module-scope device arrays, referenced ONLY inside kernels ----
__device__ float4 g_deg4[NN4];
__device__ float4 g_agg4[AGG4];
__device__ float4 g_h1_4[AGG4];
__device__ float4 g_h2_4[AGG4];          // fallback h output if d_out lacks room
__device__ float4 g_WT4[4 * D * D / 4]; // W1l^T, W1r^T, W2l^T, W2r^T
__device__ int    g_is64;                // 1 if edge_index is int64, 0 if int32

// ---------------------------------------------------------------------------
// Probe edge_index dtype: int64 data (values < 2^31) has all odd int32 words 0.
__global__ void detect_kernel(const int* __restrict__ ei32) {
    __shared__ int anyNonZero;
    if (threadIdx.x == 0) anyNonZero = 0;
    __syncthreads();
    // sample 1024 odd-position words
    int w = ei32[2 * threadIdx.x + 1];
    for (int k = 0; k < 3; k++) {
        int w2 = ei32[2 * (threadIdx.x + 256 * (k + 1)) + 1];
        w |= w2;
    }
    if (w != 0) anyNonZero = 1;
    __syncthreads();
    if (threadIdx.x == 0) g_is64 = anyNonZero ? 0 : 1;
}

__global__ void zero_kernel(int withDeg) {
    int i = blockIdx.x * blockDim.x + threadIdx.x;
    float4 z = make_float4(0.f, 0.f, 0.f, 0.f);
    if (i < AGG4) g_agg4[i] = z;
    if (withDeg && i < NN4) g_deg4[i] = z;
}

// transpose 4 64x64 weight matrices into g_WT: WT[m][k*64+j] = W[m][j*64+k]
__global__ void transpose_w(const float* __restrict__ W1l, const float* __restrict__ W1r,
                            const float* __restrict__ W2l, const float* __restrict__ W2r) {
    const float* src[4] = {W1l, W1r, W2l, W2r};
    float* WT = (float*)g_WT4;
    int t = threadIdx.x;
    for (int m = 0; m < 4; m++) {
        const float* S = src[m];
        float* T = WT + m * (D * D);
        for (int i = t; i < D * D; i += blockDim.x) {
            int j = i >> 6, k = i & 63;
            T[k * D + j] = S[i];
        }
    }
}

__device__ __forceinline__ int load_idx(const void* ei, int pos, int is64) {
    if (is64) return (int)__ldg((const long long*)ei + pos);
    return __ldg((const int*)ei + pos);
}

// scatter-sum: g_agg[dst] += feat[src]; 16 threads/edge, one float4 each
template <int LAYER>
__global__ void scatter_kernel(const float* __restrict__ x,
                               const void* __restrict__ ei) {
    int idx = blockIdx.x * blockDim.x + threadIdx.x;
    if (idx >= NE * 16) return;
    int e = idx >> 4;
    int q = idx & 15;
    int is64 = g_is64;
    int s = load_idx(ei, e, is64);
    int d = load_idx(ei, NE + e, is64);
    const float* feat = (LAYER == 0) ? x : (const float*)g_h1_4;
    float4 v = __ldg((const float4*)(feat + (size_t)s * D) + q);
    float* a = (float*)g_agg4 + (size_t)d * D + q * 4;
    atomicAdd(a + 0, v.x);
    atomicAdd(a + 1, v.y);
    atomicAdd(a + 2, v.z);
    atomicAdd(a + 3, v.w);
    if (LAYER == 0 && q == 0) atomicAdd((float*)g_deg4 + d, 1.0f);
}

// fused SAGE linear: hout = relu( (g_agg/deg) @ Wl^T + b + feat @ Wr^T )
// LAYER==0: feat = x param, writes g_h1.
// LAYER==1: feat = g_h1, writes hout (param if HPARAM else g_h2) + fused head -> out.
// block = 256 threads = 16 nodes x (16 threads of 4 channels each)
template <int LAYER, int HPARAM>
__global__ void linear_kernel(const float* __restrict__ x,
                              const float* __restrict__ b,
                              float* __restrict__ hout_p,
                              const float* __restrict__ Wh,
                              const float* __restrict__ bh,
                              float* __restrict__ out) {
    __shared__ float sm[16][D + 1];
    __shared__ float sx[16][D + 1];
    int t = threadIdx.x;
    int node0 = blockIdx.x * 16;

    const float* feat = (LAYER == 0) ? x : (const float*)g_h1_4;
    const float* agg  = (const float*)g_agg4;
    const float* deg  = (const float*)g_deg4;
    const float* WlT  = (const float*)g_WT4 + (2 * LAYER) * (D * D);
    const float* WrT  = WlT + D * D;

    {   // cooperative feature staging (coalesced float4)
        int lnl = t >> 4, c4 = t & 15;
        int node = node0 + lnl;
        float4 xv = __ldg((const float4*)(feat + (size_t)node * D) + c4);
        float4 av = __ldg((const float4*)(agg + (size_t)node * D) + c4);
        float rd = 1.0f / fmaxf(__ldg(&deg[node]), 1.0f);
        int c = c4 * 4;
        sx[lnl][c + 0] = xv.x; sx[lnl][c + 1] = xv.y;
        sx[lnl][c + 2] = xv.z; sx[lnl][c + 3] = xv.w;
        sm[lnl][c + 0] = av.x * rd; sm[lnl][c + 1] = av.y * rd;
        sm[lnl][c + 2] = av.z * rd; sm[lnl][c + 3] = av.w * rd;
    }
    __syncthreads();

    int ln = t >> 4, j4 = t & 15;
    float4 acc = __ldg((const float4*)b + j4);
    const float4* wl4 = (const float4*)WlT;
    const float4* wr4 = (const float4*)WrT;

#pragma unroll 8
    for (int k = 0; k < D; k++) {
        float4 wl = __ldg(wl4 + k * 16 + j4);
        float4 wr = __ldg(wr4 + k * 16 + j4);
        float m = sm[ln][k];
        float xk = sx[ln][k];
        acc.x += wl.x * m + wr.x * xk;
        acc.y += wl.y * m + wr.y * xk;
        acc.z += wl.z * m + wr.z * xk;
        acc.w += wl.w * m + wr.w * xk;
    }
    acc.x = fmaxf(acc.x, 0.f);
    acc.y = fmaxf(acc.y, 0.f);
    acc.z = fmaxf(acc.z, 0.f);
    acc.w = fmaxf(acc.w, 0.f);

    int node = node0 + ln;
    float* hout;
    if (LAYER == 0)      hout = (float*)g_h1_4;
    else if (HPARAM)     hout = hout_p;
    else                 hout = (float*)g_h2_4;
    ((float4*)(hout + (size_t)node * D))[j4] = acc;

    if (LAYER == 1) {  // fused head projection: width-16 shuffle reduction
        float4 wh = __ldg((const float4*)Wh + j4);
        float p = acc.x * wh.x + acc.y * wh.y + acc.z * wh.z + acc.w * wh.w;
        p += __shfl_down_sync(0xffffffffu, p, 8, 16);
        p += __shfl_down_sync(0xffffffffu, p, 4, 16);
        p += __shfl_down_sync(0xffffffffu, p, 2, 16);
        p += __shfl_down_sync(0xffffffffu, p, 1, 16);
        if (j4 == 0) out[node] = p + __ldg(bh);
    }
}

// ---------------------------------------------------------------------------
extern "C" void kernel_launch(void* const* d_in, const int* in_sizes, int n_in,
                              void* d_out, int out_size) {
    const float* x   = (const float*)d_in[0];
    const void*  ei  = d_in[1];
    const float* W1l = (const float*)d_in[2];
    const float* W1r = (const float*)d_in[3];
    const float* b1  = (const float*)d_in[4];
    const float* W2l = (const float*)d_in[5];
    const float* W2r = (const float*)d_in[6];
    const float* b2  = (const float*)d_in[7];
    const float* Wh  = (const float*)d_in[8];
    const float* bh  = (const float*)d_in[9];
    float* outp = (float*)d_out;

    const int ZG = (AGG4 + 255) / 256;
    const int SG = (NE * 16 + 255) / 256;
    const int LG = NN / 16;

    detect_kernel<<<1, 256>>>((const int*)ei);
    zero_kernel<<<ZG, 256>>>(1);
    transpose_w<<<1, 256>>>(W1l, W1r, W2l, W2r);

    // layer 1
    scatter_kernel<0><<<SG, 256>>>(x, ei);
    linear_kernel<0, 0><<<LG, 256>>>(x, b1, nullptr, nullptr, nullptr, nullptr);

    // layer 2
    zero_kernel<<<ZG, 256>>>(0);
    scatter_kernel<1><<<SG, 256>>>(nullptr, ei);
    if (out_size >= NN * (D + 1)) {
        // tuple (out, h): out at [0, NN), h at [NN, NN + NN*D)
        linear_kernel<1, 1><<<LG, 256>>>(nullptr, b2, outp + NN, Wh, bh, outp);
    } else {
        linear_kernel<1, 0><<<LG, 256>>>(nullptr, b2, nullptr, Wh, bh, outp);
    }
}

// round 6
// speedup vs baseline: 1.8325x; 1.8325x over previous
#include <cuda_runtime.h>

#define NN 100000
#define NE 1280000
#define D 64
#define NBLK ((NN + 1023) / 1024)   // 98 scan blocks

// ---- scratch: module-scope device arrays, referenced ONLY inside kernels ----
__device__ int    g_cnt[NN];             // in-degree histogram
__device__ int    g_ptr[NN];             // CSR exclusive offsets
__device__ int    g_pos[NN];             // fill cursors
__device__ int    g_srcl[NE];            // CSR source-node list
__device__ int    g_blk[128];            // scan block sums
__device__ float4 g_h1_4[NN * D / 4];    // layer-1 hidden
__device__ float4 g_h2_4[NN * D / 4];    // fallback h output
__device__ float4 g_WT4[4 * D * D / 4];  // W1l^T, W1r^T, W2l^T, W2r^T
__device__ int    g_is64;                // edge_index dtype flag

// ---------------------------------------------------------------------------
// Probe edge_index dtype: int64 data (values < 2^31) has all odd int32 words 0.
__global__ void detect_kernel(const int* __restrict__ ei32) {
    __shared__ int anyNonZero;
    if (threadIdx.x == 0) anyNonZero = 0;
    __syncthreads();
    int w = ei32[2 * threadIdx.x + 1];
    for (int k = 0; k < 3; k++) w |= ei32[2 * (threadIdx.x + 256 * (k + 1)) + 1];
    if (w != 0) anyNonZero = 1;
    __syncthreads();
    if (threadIdx.x == 0) g_is64 = anyNonZero ? 0 : 1;
}

__device__ __forceinline__ int load_idx(const void* ei, int pos, int is64) {
    if (is64) return (int)__ldg((const long long*)ei + pos);
    return __ldg((const int*)ei + pos);
}

__global__ void zero_cnt_kernel() {
    int i = blockIdx.x * blockDim.x + threadIdx.x;
    if (i < NN) g_cnt[i] = 0;
}

// transpose 4 64x64 weight matrices into g_WT: WT[m][k*64+j] = W[m][j*64+k]
__global__ void transpose_w(const float* __restrict__ W1l, const float* __restrict__ W1r,
                            const float* __restrict__ W2l, const float* __restrict__ W2r) {
    const float* src[4] = {W1l, W1r, W2l, W2r};
    float* WT = (float*)g_WT4;
    int t = threadIdx.x;
    for (int m = 0; m < 4; m++) {
        const float* S = src[m];
        float* T = WT + m * (D * D);
        for (int i = t; i < D * D; i += blockDim.x) {
            int j = i >> 6, k = i & 63;
            T[k * D + j] = S[i];
        }
    }
}

__global__ void hist_kernel(const void* __restrict__ ei) {
    int e = blockIdx.x * blockDim.x + threadIdx.x;
    if (e >= NE) return;
    int d = load_idx(ei, NE + e, g_is64);
    atomicAdd(&g_cnt[d], 1);
}

// block-level exclusive scan of g_cnt -> g_ptr, block totals -> g_blk
__global__ void scan1_kernel() {
    int i = blockIdx.x * 1024 + threadIdx.x;
    int v = (i < NN) ? g_cnt[i] : 0;
    int lane = threadIdx.x & 31, wid = threadIdx.x >> 5;
    int sv = v;
#pragma unroll
    for (int o = 1; o < 32; o <<= 1) {
        int n = __shfl_up_sync(0xffffffffu, sv, o);
        if (lane >= o) sv += n;
    }
    __shared__ int ws[32];
    if (lane == 31) ws[wid] = sv;
    __syncthreads();
    if (wid == 0) {
        int wv = ws[lane];
#pragma unroll
        for (int o = 1; o < 32; o <<= 1) {
            int n = __shfl_up_sync(0xffffffffu, wv, o);
            if (lane >= o) wv += n;
        }
        ws[lane] = wv;
    }
    __syncthreads();
    int off = wid ? ws[wid - 1] : 0;
    int incl = sv + off;
    if (i < NN) g_ptr[i] = incl - v;   // exclusive
    if (threadIdx.x == 1023) g_blk[blockIdx.x] = incl;
}

// exclusive scan of the 98 block sums (single 128-thread block)
__global__ void scan2_kernel() {
    int t = threadIdx.x;
    int v = (t < NBLK) ? g_blk[t] : 0;
    int lane = t & 31, wid = t >> 5;
    int sv = v;
#pragma unroll
    for (int o = 1; o < 32; o <<= 1) {
        int n = __shfl_up_sync(0xffffffffu, sv, o);
        if (lane >= o) sv += n;
    }
    __shared__ int ws[4];
    if (lane == 31) ws[wid] = sv;
    __syncthreads();
    int off = 0;
    for (int w = 0; w < wid; w++) off += ws[w];
    if (t < NBLK) g_blk[t] = sv + off - v;  // exclusive
}

__global__ void scan3_kernel() {
    int i = blockIdx.x * 1024 + threadIdx.x;
    if (i >= NN) return;
    int p = g_ptr[i] + g_blk[blockIdx.x];
    g_ptr[i] = p;
    g_pos[i] = p;
}

__global__ void fill_kernel(const void* __restrict__ ei) {
    int e = blockIdx.x * blockDim.x + threadIdx.x;
    if (e >= NE) return;
    int is64 = g_is64;
    int s = load_idx(ei, e, is64);
    int d = load_idx(ei, NE + e, is64);
    int p = atomicAdd(&g_pos[d], 1);
    g_srcl[p] = s;
}

// ---------------------------------------------------------------------------
// Fused layer: CSR gather-mean + hout = relu(mean @ Wl^T + b + feat @ Wr^T)
// LAYER==0: feat = x param, writes g_h1.  LAYER==1: feat = g_h1, + fused head.
// block = 256 threads = 16 nodes x (16 threads of one float4 channel group)
template <int LAYER, int HPARAM>
__global__ void sage_layer(const float* __restrict__ x,
                           const float* __restrict__ b,
                           float* __restrict__ hout_p,
                           const float* __restrict__ Wh,
                           const float* __restrict__ bh,
                           float* __restrict__ out) {
    __shared__ float sm[16][D + 1];
    __shared__ float sx[16][D + 1];
    int t = threadIdx.x;
    int ln = t >> 4, q = t & 15;
    int node = blockIdx.x * 16 + ln;

    const float* feat = (LAYER == 0) ? x : (const float*)g_h1_4;

    // gather-mean aggregation: 16 threads walk this node's in-edge list
    int beg = __ldg(&g_ptr[node]);
    int cnt = __ldg(&g_cnt[node]);
    int end = beg + cnt;
    float4 acc = make_float4(0.f, 0.f, 0.f, 0.f);
    int e = beg;
    for (; e + 1 < end; e += 2) {
        int s0 = __ldg(&g_srcl[e]);
        int s1 = __ldg(&g_srcl[e + 1]);
        float4 v0 = __ldg((const float4*)(feat + (size_t)s0 * D) + q);
        float4 v1 = __ldg((const float4*)(feat + (size_t)s1 * D) + q);
        acc.x += v0.x + v1.x; acc.y += v0.y + v1.y;
        acc.z += v0.z + v1.z; acc.w += v0.w + v1.w;
    }
    if (e < end) {
        int s0 = __ldg(&g_srcl[e]);
        float4 v0 = __ldg((const float4*)(feat + (size_t)s0 * D) + q);
        acc.x += v0.x; acc.y += v0.y; acc.z += v0.z; acc.w += v0.w;
    }
    float rd = 1.0f / (float)max(cnt, 1);
    float4 xv = __ldg((const float4*)(feat + (size_t)node * D) + q);
    int c = q * 4;
    sm[ln][c + 0] = acc.x * rd; sm[ln][c + 1] = acc.y * rd;
    sm[ln][c + 2] = acc.z * rd; sm[ln][c + 3] = acc.w * rd;
    sx[ln][c + 0] = xv.x; sx[ln][c + 1] = xv.y;
    sx[ln][c + 2] = xv.z; sx[ln][c + 3] = xv.w;
    __syncthreads();

    const float4* wl4 = (const float4*)((const float*)g_WT4 + (2 * LAYER) * (D * D));
    const float4* wr4 = wl4 + (D * D) / 4;
    float4 o4 = __ldg((const float4*)b + q);

#pragma unroll 8
    for (int k = 0; k < D; k++) {
        float4 wl = __ldg(wl4 + k * 16 + q);
        float4 wr = __ldg(wr4 + k * 16 + q);
        float m = sm[ln][k];
        float xk = sx[ln][k];
        o4.x += wl.x * m + wr.x * xk;
        o4.y += wl.y * m + wr.y * xk;
        o4.z += wl.z * m + wr.z * xk;
        o4.w += wl.w * m + wr.w * xk;
    }
    o4.x = fmaxf(o4.x, 0.f); o4.y = fmaxf(o4.y, 0.f);
    o4.z = fmaxf(o4.z, 0.f); o4.w = fmaxf(o4.w, 0.f);

    float* hout;
    if (LAYER == 0)  hout = (float*)g_h1_4;
    else if (HPARAM) hout = hout_p;
    else             hout = (float*)g_h2_4;
    ((float4*)(hout + (size_t)node * D))[q] = o4;

    if (LAYER == 1) {  // fused head projection: width-16 shuffle reduction
        float4 wh = __ldg((const float4*)Wh + q);
        float p = o4.x * wh.x + o4.y * wh.y + o4.z * wh.z + o4.w * wh.w;
        p += __shfl_down_sync(0xffffffffu, p, 8, 16);
        p += __shfl_down_sync(0xffffffffu, p, 4, 16);
        p += __shfl_down_sync(0xffffffffu, p, 2, 16);
        p += __shfl_down_sync(0xffffffffu, p, 1, 16);
        if (q == 0) out[node] = p + __ldg(bh);
    }
}

// ---------------------------------------------------------------------------
extern "C" void kernel_launch(void* const* d_in, const int* in_sizes, int n_in,
                              void* d_out, int out_size) {
    const float* x   = (const float*)d_in[0];
    const void*  ei  = d_in[1];
    const float* W1l = (const float*)d_in[2];
    const float* W1r = (const float*)d_in[3];
    const float* b1  = (const float*)d_in[4];
    const float* W2l = (const float*)d_in[5];
    const float* W2r = (const float*)d_in[6];
    const float* b2  = (const float*)d_in[7];
    const float* Wh  = (const float*)d_in[8];
    const float* bh  = (const float*)d_in[9];
    float* outp = (float*)d_out;

    const int EG = (NE + 255) / 256;
    const int LG = NN / 16;

    detect_kernel<<<1, 256>>>((const int*)ei);
    zero_cnt_kernel<<<(NN + 1023) / 1024, 1024>>>();
    transpose_w<<<1, 256>>>(W1l, W1r, W2l, W2r);

    // CSR build (reused by both layers)
    hist_kernel<<<EG, 256>>>(ei);
    scan1_kernel<<<NBLK, 1024>>>();
    scan2_kernel<<<1, 128>>>();
    scan3_kernel<<<NBLK, 1024>>>();
    fill_kernel<<<EG, 256>>>(ei);

    // fused layers
    sage_layer<0, 0><<<LG, 256>>>(x, b1, nullptr, nullptr, nullptr, nullptr);
    if (out_size >= NN * (D + 1)) {
        sage_layer<1, 1><<<LG, 256>>>(nullptr, b2, outp + NN, Wh, bh, outp);
    } else {
        sage_layer<1, 0><<<LG, 256>>>(nullptr, b2, nullptr, Wh, bh, outp);
    }
}

// round 7
// speedup vs baseline: 1.8462x; 1.0075x over previous
#include <cuda_runtime.h>

#define NN 100000
#define NE 1280000
#define D 64
#define NBLK ((NN + 1023) / 1024)   // 98 scan blocks

// ---- scratch: module-scope device arrays, referenced ONLY inside kernels ----
__device__ int    g_cnt[NN];             // in-degree histogram
__device__ int    g_ptr[NN];             // CSR exclusive offsets
__device__ int    g_pos[NN];             // fill cursors
__device__ int    g_srcl[NE];            // CSR source-node list
__device__ int    g_blk[128];            // scan block sums
__device__ float4 g_h1_4[NN * D / 4];    // layer-1 hidden
__device__ float4 g_h2_4[NN * D / 4];    // fallback h output
__device__ float4 g_WT4[4 * D * D / 4];  // W1l^T, W1r^T, W2l^T, W2r^T
__device__ int    g_is64;                // edge_index dtype flag

// ---------------------------------------------------------------------------
// Probe edge_index dtype: int64 data (values < 2^31) has all odd int32 words 0.
__global__ void detect_kernel(const int* __restrict__ ei32) {
    __shared__ int anyNonZero;
    if (threadIdx.x == 0) anyNonZero = 0;
    __syncthreads();
    int w = ei32[2 * threadIdx.x + 1];
    for (int k = 0; k < 3; k++) w |= ei32[2 * (threadIdx.x + 256 * (k + 1)) + 1];
    if (w != 0) anyNonZero = 1;
    __syncthreads();
    if (threadIdx.x == 0) g_is64 = anyNonZero ? 0 : 1;
}

__device__ __forceinline__ int load_idx(const void* ei, int pos, int is64) {
    if (is64) return (int)__ldg((const long long*)ei + pos);
    return __ldg((const int*)ei + pos);
}

__global__ void zero_cnt_kernel() {
    int i = blockIdx.x * blockDim.x + threadIdx.x;
    if (i < NN) g_cnt[i] = 0;
}

// transpose 4 64x64 weight matrices into g_WT: WT[m][k*64+j] = W[m][j*64+k]
__global__ void transpose_w(const float* __restrict__ W1l, const float* __restrict__ W1r,
                            const float* __restrict__ W2l, const float* __restrict__ W2r) {
    const float* src[4] = {W1l, W1r, W2l, W2r};
    float* WT = (float*)g_WT4;
    int t = threadIdx.x;
    for (int m = 0; m < 4; m++) {
        const float* S = src[m];
        float* T = WT + m * (D * D);
        for (int i = t; i < D * D; i += blockDim.x) {
            int j = i >> 6, k = i & 63;
            T[k * D + j] = S[i];
        }
    }
}

__global__ void hist_kernel(const void* __restrict__ ei) {
    int e = blockIdx.x * blockDim.x + threadIdx.x;
    if (e >= NE) return;
    int d = load_idx(ei, NE + e, g_is64);
    atomicAdd(&g_cnt[d], 1);
}

// block-level exclusive scan of g_cnt -> g_ptr, block totals -> g_blk
__global__ void scan1_kernel() {
    int i = blockIdx.x * 1024 + threadIdx.x;
    int v = (i < NN) ? g_cnt[i] : 0;
    int lane = threadIdx.x & 31, wid = threadIdx.x >> 5;
    int sv = v;
#pragma unroll
    for (int o = 1; o < 32; o <<= 1) {
        int n = __shfl_up_sync(0xffffffffu, sv, o);
        if (lane >= o) sv += n;
    }
    __shared__ int ws[32];
    if (lane == 31) ws[wid] = sv;
    __syncthreads();
    if (wid == 0) {
        int wv = ws[lane];
#pragma unroll
        for (int o = 1; o < 32; o <<= 1) {
            int n = __shfl_up_sync(0xffffffffu, wv, o);
            if (lane >= o) wv += n;
        }
        ws[lane] = wv;
    }
    __syncthreads();
    int off = wid ? ws[wid - 1] : 0;
    int incl = sv + off;
    if (i < NN) g_ptr[i] = incl - v;   // exclusive
    if (threadIdx.x == 1023) g_blk[blockIdx.x] = incl;
}

// exclusive scan of the 98 block sums (single 128-thread block)
__global__ void scan2_kernel() {
    int t = threadIdx.x;
    int v = (t < NBLK) ? g_blk[t] : 0;
    int lane = t & 31, wid = t >> 5;
    int sv = v;
#pragma unroll
    for (int o = 1; o < 32; o <<= 1) {
        int n = __shfl_up_sync(0xffffffffu, sv, o);
        if (lane >= o) sv += n;
    }
    __shared__ int ws[4];
    if (lane == 31) ws[wid] = sv;
    __syncthreads();
    int off = 0;
    for (int w = 0; w < wid; w++) off += ws[w];
    if (t < NBLK) g_blk[t] = sv + off - v;  // exclusive
}

__global__ void scan3_kernel() {
    int i = blockIdx.x * 1024 + threadIdx.x;
    if (i >= NN) return;
    int p = g_ptr[i] + g_blk[blockIdx.x];
    g_ptr[i] = p;
    g_pos[i] = p;
}

__global__ void fill_kernel(const void* __restrict__ ei) {
    int e = blockIdx.x * blockDim.x + threadIdx.x;
    if (e >= NE) return;
    int is64 = g_is64;
    int s = load_idx(ei, e, is64);
    int d = load_idx(ei, NE + e, is64);
    int p = atomicAdd(&g_pos[d], 1);
    g_srcl[p] = s;
}

// ---------------------------------------------------------------------------
// Fused layer: CSR gather-mean + hout = relu(mean @ Wl^T + b + feat @ Wr^T)
// LAYER==0: feat = x param, writes g_h1.  LAYER==1: feat = g_h1, + fused head.
// block = 256 threads = 16 nodes x (16 threads of one float4 channel group)
template <int LAYER, int HPARAM>
__global__ void __launch_bounds__(256) sage_layer(
                           const float* __restrict__ x,
                           const float* __restrict__ b,
                           float* __restrict__ hout_p,
                           const float* __restrict__ Wh,
                           const float* __restrict__ bh,
                           float* __restrict__ out) {
    __shared__ float sm[16][D + 1];
    __shared__ float sx[16][D + 1];
    int t = threadIdx.x;
    int ln = t >> 4, q = t & 15;
    int node = blockIdx.x * 16 + ln;

    const float* feat = (LAYER == 0) ? x : (const float*)g_h1_4;

    // gather-mean aggregation: 16 threads walk this node's in-edge list,
    // unrolled x4 so each thread keeps ~8 loads in flight (MLP).
    int beg = __ldg(&g_ptr[node]);
    int cnt = __ldg(&g_cnt[node]);
    int end = beg + cnt;
    float4 acc = make_float4(0.f, 0.f, 0.f, 0.f);
    int e = beg;
    for (; e + 3 < end; e += 4) {
        int s0 = __ldg(&g_srcl[e + 0]);
        int s1 = __ldg(&g_srcl[e + 1]);
        int s2 = __ldg(&g_srcl[e + 2]);
        int s3 = __ldg(&g_srcl[e + 3]);
        float4 v0 = __ldg((const float4*)(feat + (size_t)s0 * D) + q);
        float4 v1 = __ldg((const float4*)(feat + (size_t)s1 * D) + q);
        float4 v2 = __ldg((const float4*)(feat + (size_t)s2 * D) + q);
        float4 v3 = __ldg((const float4*)(feat + (size_t)s3 * D) + q);
        acc.x += (v0.x + v1.x) + (v2.x + v3.x);
        acc.y += (v0.y + v1.y) + (v2.y + v3.y);
        acc.z += (v0.z + v1.z) + (v2.z + v3.z);
        acc.w += (v0.w + v1.w) + (v2.w + v3.w);
    }
    for (; e < end; e++) {
        int s0 = __ldg(&g_srcl[e]);
        float4 v0 = __ldg((const float4*)(feat + (size_t)s0 * D) + q);
        acc.x += v0.x; acc.y += v0.y; acc.z += v0.z; acc.w += v0.w;
    }
    float rd = 1.0f / (float)max(cnt, 1);
    float4 xv = __ldg((const float4*)(feat + (size_t)node * D) + q);
    int c = q * 4;
    sm[ln][c + 0] = acc.x * rd; sm[ln][c + 1] = acc.y * rd;
    sm[ln][c + 2] = acc.z * rd; sm[ln][c + 3] = acc.w * rd;
    sx[ln][c + 0] = xv.x; sx[ln][c + 1] = xv.y;
    sx[ln][c + 2] = xv.z; sx[ln][c + 3] = xv.w;
    __syncthreads();

    const float4* wl4 = (const float4*)((const float*)g_WT4 + (2 * LAYER) * (D * D));
    const float4* wr4 = wl4 + (D * D) / 4;
    float4 o4 = __ldg((const float4*)b + q);

#pragma unroll 8
    for (int k = 0; k < D; k++) {
        float4 wl = __ldg(wl4 + k * 16 + q);
        float4 wr = __ldg(wr4 + k * 16 + q);
        float m = sm[ln][k];
        float xk = sx[ln][k];
        o4.x += wl.x * m + wr.x * xk;
        o4.y += wl.y * m + wr.y * xk;
        o4.z += wl.z * m + wr.z * xk;
        o4.w += wl.w * m + wr.w * xk;
    }
    o4.x = fmaxf(o4.x, 0.f); o4.y = fmaxf(o4.y, 0.f);
    o4.z = fmaxf(o4.z, 0.f); o4.w = fmaxf(o4.w, 0.f);

    float* hout;
    if (LAYER == 0)  hout = (float*)g_h1_4;
    else if (HPARAM) hout = hout_p;
    else             hout = (float*)g_h2_4;
    ((float4*)(hout + (size_t)node * D))[q] = o4;

    if (LAYER == 1) {  // fused head projection: width-16 shuffle reduction
        float4 wh = __ldg((const float4*)Wh + q);
        float p = o4.x * wh.x + o4.y * wh.y + o4.z * wh.z + o4.w * wh.w;
        p += __shfl_down_sync(0xffffffffu, p, 8, 16);
        p += __shfl_down_sync(0xffffffffu, p, 4, 16);
        p += __shfl_down_sync(0xffffffffu, p, 2, 16);
        p += __shfl_down_sync(0xffffffffu, p, 1, 16);
        if (q == 0) out[node] = p + __ldg(bh);
    }
}

// ---------------------------------------------------------------------------
extern "C" void kernel_launch(void* const* d_in, const int* in_sizes, int n_in,
                              void* d_out, int out_size) {
    const float* x   = (const float*)d_in[0];
    const void*  ei  = d_in[1];
    const float* W1l = (const float*)d_in[2];
    const float* W1r = (const float*)d_in[3];
    const float* b1  = (const float*)d_in[4];
    const float* W2l = (const float*)d_in[5];
    const float* W2r = (const float*)d_in[6];
    const float* b2  = (const float*)d_in[7];
    const float* Wh  = (const float*)d_in[8];
    const float* bh  = (const float*)d_in[9];
    float* outp = (float*)d_out;

    const int EG = (NE + 255) / 256;
    const int LG = NN / 16;

    detect_kernel<<<1, 256>>>((const int*)ei);
    zero_cnt_kernel<<<(NN + 1023) / 1024, 1024>>>();
    transpose_w<<<1, 256>>>(W1l, W1r, W2l, W2r);

    // CSR build (reused by both layers)
    hist_kernel<<<EG, 256>>>(ei);
    scan1_kernel<<<NBLK, 1024>>>();
    scan2_kernel<<<1, 128>>>();
    scan3_kernel<<<NBLK, 1024>>>();
    fill_kernel<<<EG, 256>>>(ei);

    // fused layers
    sage_layer<0, 0><<<LG, 256>>>(x, b1, nullptr, nullptr, nullptr, nullptr);
    if (out_size >= NN * (D + 1)) {
        sage_layer<1, 1><<<LG, 256>>>(nullptr, b2, outp + NN, Wh, bh, outp);
    } else {
        sage_layer<1, 0><<<LG, 256>>>(nullptr, b2, nullptr, Wh, bh, outp);
    }
}

// round 8
// speedup vs baseline: 2.6488x; 1.4347x over previous
#include <cuda_runtime.h>

#define NN 100000
#define NE 1280000
#define D 64
#define NBLK ((NN + 1023) / 1024)   // 98 scan blocks
#define NPB 64                       // nodes per block in sage_layer
#define SMS 66                       // smT row stride (even -> 8B-aligned pairs)

// ---- scratch: module-scope device arrays, referenced ONLY inside kernels ----
__device__ int    g_cnt[NN];             // in-degree histogram
__device__ int    g_ptr[NN];             // CSR exclusive offsets
__device__ int    g_pos[NN];             // fill cursors
__device__ int    g_srcl[NE];            // CSR source-node list
__device__ int    g_blk[128];            // scan block sums
__device__ float4 g_h1_4[NN * D / 4];    // layer-1 hidden
__device__ float4 g_h2_4[NN * D / 4];    // fallback h output
__device__ float4 g_WT4[4 * D * D / 4];  // W1l^T, W1r^T, W2l^T, W2r^T
__device__ int    g_is64;                // edge_index dtype flag

typedef unsigned long long ull;

__device__ __forceinline__ ull pack2(float f) {
    ull r;
    unsigned u = __float_as_uint(f);
    asm("mov.b64 %0, {%1, %1};" : "=l"(r) : "r"(u));
    return r;
}
__device__ __forceinline__ void ffma2(ull& acc, ull a, ull b) {
    asm("fma.rn.f32x2 %0, %1, %2, %0;" : "+l"(acc) : "l"(a), "l"(b));
}
__device__ __forceinline__ void unpack2(ull v, float& lo, float& hi) {
    unsigned a, b;
    asm("mov.b64 {%0, %1}, %2;" : "=r"(a), "=r"(b) : "l"(v));
    lo = __uint_as_float(a);
    hi = __uint_as_float(b);
}

// ---------------------------------------------------------------------------
// Probe edge_index dtype: int64 data (values < 2^31) has all odd int32 words 0.
__global__ void detect_kernel(const int* __restrict__ ei32) {
    __shared__ int anyNonZero;
    if (threadIdx.x == 0) anyNonZero = 0;
    __syncthreads();
    int w = ei32[2 * threadIdx.x + 1];
    for (int k = 0; k < 3; k++) w |= ei32[2 * (threadIdx.x + 256 * (k + 1)) + 1];
    if (w != 0) anyNonZero = 1;
    __syncthreads();
    if (threadIdx.x == 0) g_is64 = anyNonZero ? 0 : 1;
}

__device__ __forceinline__ int load_idx(const void* ei, int pos, int is64) {
    if (is64) return (int)__ldg((const long long*)ei + pos);
    return __ldg((const int*)ei + pos);
}

__global__ void zero_cnt_kernel() {
    int i = blockIdx.x * blockDim.x + threadIdx.x;
    if (i < NN) g_cnt[i] = 0;
}

// transpose 4 64x64 weight matrices into g_WT: WT[m][k*64+j] = W[m][j*64+k]
__global__ void transpose_w(const float* __restrict__ W1l, const float* __restrict__ W1r,
                            const float* __restrict__ W2l, const float* __restrict__ W2r) {
    const float* src[4] = {W1l, W1r, W2l, W2r};
    float* WT = (float*)g_WT4;
    int t = threadIdx.x;
    for (int m = 0; m < 4; m++) {
        const float* S = src[m];
        float* T = WT + m * (D * D);
        for (int i = t; i < D * D; i += blockDim.x) {
            int j = i >> 6, k = i & 63;
            T[k * D + j] = S[i];
        }
    }
}

__global__ void hist_kernel(const void* __restrict__ ei) {
    int e = blockIdx.x * blockDim.x + threadIdx.x;
    if (e >= NE) return;
    int d = load_idx(ei, NE + e, g_is64);
    atomicAdd(&g_cnt[d], 1);
}

// block-level exclusive scan of g_cnt -> g_ptr, block totals -> g_blk
__global__ void scan1_kernel() {
    int i = blockIdx.x * 1024 + threadIdx.x;
    int v = (i < NN) ? g_cnt[i] : 0;
    int lane = threadIdx.x & 31, wid = threadIdx.x >> 5;
    int sv = v;
#pragma unroll
    for (int o = 1; o < 32; o <<= 1) {
        int n = __shfl_up_sync(0xffffffffu, sv, o);
        if (lane >= o) sv += n;
    }
    __shared__ int ws[32];
    if (lane == 31) ws[wid] = sv;
    __syncthreads();
    if (wid == 0) {
        int wv = ws[lane];
#pragma unroll
        for (int o = 1; o < 32; o <<= 1) {
            int n = __shfl_up_sync(0xffffffffu, wv, o);
            if (lane >= o) wv += n;
        }
        ws[lane] = wv;
    }
    __syncthreads();
    int off = wid ? ws[wid - 1] : 0;
    int incl = sv + off;
    if (i < NN) g_ptr[i] = incl - v;   // exclusive
    if (threadIdx.x == 1023) g_blk[blockIdx.x] = incl;
}

// exclusive scan of the 98 block sums (single 128-thread block)
__global__ void scan2_kernel() {
    int t = threadIdx.x;
    int v = (t < NBLK) ? g_blk[t] : 0;
    int lane = t & 31, wid = t >> 5;
    int sv = v;
#pragma unroll
    for (int o = 1; o < 32; o <<= 1) {
        int n = __shfl_up_sync(0xffffffffu, sv, o);
        if (lane >= o) sv += n;
    }
    __shared__ int ws[4];
    if (lane == 31) ws[wid] = sv;
    __syncthreads();
    int off = 0;
    for (int w = 0; w < wid; w++) off += ws[w];
    if (t < NBLK) g_blk[t] = sv + off - v;  // exclusive
}

__global__ void scan3_kernel() {
    int i = blockIdx.x * 1024 + threadIdx.x;
    if (i >= NN) return;
    int p = g_ptr[i] + g_blk[blockIdx.x];
    g_ptr[i] = p;
    g_pos[i] = p;
}

__global__ void fill_kernel(const void* __restrict__ ei) {
    int e = blockIdx.x * blockDim.x + threadIdx.x;
    if (e >= NE) return;
    int is64 = g_is64;
    int s = load_idx(ei, e, is64);
    int d = load_idx(ei, NE + e, is64);
    int p = atomicAdd(&g_pos[d], 1);
    g_srcl[p] = s;
}

// ---------------------------------------------------------------------------
// Fused layer: CSR gather-mean + hout = relu(mean @ Wl^T + b + feat @ Wr^T)
// 64 nodes/block; 256 threads = 16 channel-groups (q) x 16 slots; each thread
// owns 4 consecutive nodes and 4 channels. Linear phase uses packed f32x2 FMA
// with node-pairs as the SIMD axis (multipliers come pair-wise from smT).
template <int LAYER, int HPARAM>
__global__ void __launch_bounds__(256) sage_layer(
                           const float* __restrict__ x,
                           const float* __restrict__ b,
                           float* __restrict__ hout_p,
                           const float* __restrict__ Wh,
                           const float* __restrict__ bh,
                           float* __restrict__ out) {
    __shared__ float smM[D * SMS];   // smM[k*SMS + local_node] : mean
    __shared__ float smX[D * SMS];   // smX[k*SMS + local_node] : root feature
    int t = threadIdx.x;
    int q = t & 15, slot = t >> 4;
    int node0 = blockIdx.x * NPB;
    int s4 = slot * 4;

    const float* feat = (LAYER == 0) ? x : (const float*)g_h1_4;

    // ---- gather-mean for this thread's 4 nodes, channels 4q..4q+3 ----
#pragma unroll
    for (int i = 0; i < 4; i++) {
        int nl = s4 + i;
        int node = node0 + nl;
        float4 acc = make_float4(0.f, 0.f, 0.f, 0.f);
        int cnt = 0;
        if (node < NN) {
            int beg = __ldg(&g_ptr[node]);
            cnt = __ldg(&g_cnt[node]);
            int end = beg + cnt;
            int e = beg;
            for (; e + 3 < end; e += 4) {
                int s0 = __ldg(&g_srcl[e + 0]);
                int s1 = __ldg(&g_srcl[e + 1]);
                int s2 = __ldg(&g_srcl[e + 2]);
                int s3 = __ldg(&g_srcl[e + 3]);
                float4 v0 = __ldg((const float4*)(feat + (size_t)s0 * D) + q);
                float4 v1 = __ldg((const float4*)(feat + (size_t)s1 * D) + q);
                float4 v2 = __ldg((const float4*)(feat + (size_t)s2 * D) + q);
                float4 v3 = __ldg((const float4*)(feat + (size_t)s3 * D) + q);
                acc.x += (v0.x + v1.x) + (v2.x + v3.x);
                acc.y += (v0.y + v1.y) + (v2.y + v3.y);
                acc.z += (v0.z + v1.z) + (v2.z + v3.z);
                acc.w += (v0.w + v1.w) + (v2.w + v3.w);
            }
            for (; e < end; e++) {
                int s0 = __ldg(&g_srcl[e]);
                float4 v0 = __ldg((const float4*)(feat + (size_t)s0 * D) + q);
                acc.x += v0.x; acc.y += v0.y; acc.z += v0.z; acc.w += v0.w;
            }
            float rd = 1.0f / (float)max(cnt, 1);
            float4 xv = __ldg((const float4*)(feat + (size_t)node * D) + q);
            int c = q * 4;
            smM[(c + 0) * SMS + nl] = acc.x * rd;
            smM[(c + 1) * SMS + nl] = acc.y * rd;
            smM[(c + 2) * SMS + nl] = acc.z * rd;
            smM[(c + 3) * SMS + nl] = acc.w * rd;
            smX[(c + 0) * SMS + nl] = xv.x;
            smX[(c + 1) * SMS + nl] = xv.y;
            smX[(c + 2) * SMS + nl] = xv.z;
            smX[(c + 3) * SMS + nl] = xv.w;
        }
    }
    __syncthreads();

    // ---- linear phase: 4 channels x 4 nodes per thread, f32x2 over node pairs
    const float4* wl4 = (const float4*)((const float*)g_WT4 + (2 * LAYER) * (D * D));
    const float4* wr4 = wl4 + (D * D) / 4;
    float4 bb = __ldg((const float4*)b + q);
    ull a0x = pack2(bb.x), a0y = pack2(bb.y), a0z = pack2(bb.z), a0w = pack2(bb.w);
    ull a1x = a0x, a1y = a0y, a1z = a0z, a1w = a0w;

#pragma unroll 4
    for (int k = 0; k < D; k++) {
        float4 wl = __ldg(wl4 + k * 16 + q);
        float4 wr = __ldg(wr4 + k * 16 + q);
        ull wlx = pack2(wl.x), wly = pack2(wl.y), wlz = pack2(wl.z), wlw = pack2(wl.w);
        ull wrx = pack2(wr.x), wry = pack2(wr.y), wrz = pack2(wr.z), wrw = pack2(wr.w);
        ull m0 = *(const ull*)&smM[k * SMS + s4];
        ull m1 = *(const ull*)&smM[k * SMS + s4 + 2];
        ull x0 = *(const ull*)&smX[k * SMS + s4];
        ull x1 = *(const ull*)&smX[k * SMS + s4 + 2];
        ffma2(a0x, wlx, m0); ffma2(a0x, wrx, x0);
        ffma2(a0y, wly, m0); ffma2(a0y, wry, x0);
        ffma2(a0z, wlz, m0); ffma2(a0z, wrz, x0);
        ffma2(a0w, wlw, m0); ffma2(a0w, wrw, x0);
        ffma2(a1x, wlx, m1); ffma2(a1x, wrx, x1);
        ffma2(a1y, wly, m1); ffma2(a1y, wry, x1);
        ffma2(a1z, wlz, m1); ffma2(a1z, wrz, x1);
        ffma2(a1w, wlw, m1); ffma2(a1w, wrw, x1);
    }

    // ---- epilogue: unpack, relu, store h, fused head ----
    float o[4][4];  // [node i][channel j]
    unpack2(a0x, o[0][0], o[1][0]); unpack2(a0y, o[0][1], o[1][1]);
    unpack2(a0z, o[0][2], o[1][2]); unpack2(a0w, o[0][3], o[1][3]);
    unpack2(a1x, o[2][0], o[3][0]); unpack2(a1y, o[2][1], o[3][1]);
    unpack2(a1z, o[2][2], o[3][2]); unpack2(a1w, o[2][3], o[3][3]);
#pragma unroll
    for (int i = 0; i < 4; i++)
#pragma unroll
        for (int j = 0; j < 4; j++) o[i][j] = fmaxf(o[i][j], 0.f);

    float* hout;
    if (LAYER == 0)  hout = (float*)g_h1_4;
    else if (HPARAM) hout = hout_p;
    else             hout = (float*)g_h2_4;

#pragma unroll
    for (int i = 0; i < 4; i++) {
        int node = node0 + s4 + i;
        if (node < NN) {
            float4 v = make_float4(o[i][0], o[i][1], o[i][2], o[i][3]);
            ((float4*)(hout + (size_t)node * D))[q] = v;
        }
    }

    if (LAYER == 1) {  // head: out[n] = dot(h[n], Wh) + bh, width-16 reduction
        float4 wh = __ldg((const float4*)Wh + q);
        float p[4];
#pragma unroll
        for (int i = 0; i < 4; i++) {
            p[i] = o[i][0] * wh.x + o[i][1] * wh.y + o[i][2] * wh.z + o[i][3] * wh.w;
            p[i] += __shfl_down_sync(0xffffffffu, p[i], 8, 16);
            p[i] += __shfl_down_sync(0xffffffffu, p[i], 4, 16);
            p[i] += __shfl_down_sync(0xffffffffu, p[i], 2, 16);
            p[i] += __shfl_down_sync(0xffffffffu, p[i], 1, 16);
        }
        if (q == 0) {
            float bhv = __ldg(bh);
#pragma unroll
            for (int i = 0; i < 4; i++) {
                int node = node0 + s4 + i;
                if (node < NN) out[node] = p[i] + bhv;
            }
        }
    }
}

// ---------------------------------------------------------------------------
extern "C" void kernel_launch(void* const* d_in, const int* in_sizes, int n_in,
                              void* d_out, int out_size) {
    const float* x   = (const float*)d_in[0];
    const void*  ei  = d_in[1];
    const float* W1l = (const float*)d_in[2];
    const float* W1r = (const float*)d_in[3];
    const float* b1  = (const float*)d_in[4];
    const float* W2l = (const float*)d_in[5];
    const float* W2r = (const float*)d_in[6];
    const float* b2  = (const float*)d_in[7];
    const float* Wh  = (const float*)d_in[8];
    const float* bh  = (const float*)d_in[9];
    float* outp = (float*)d_out;

    const int EG = (NE + 255) / 256;
    const int LG = (NN + NPB - 1) / NPB;

    detect_kernel<<<1, 256>>>((const int*)ei);
    zero_cnt_kernel<<<(NN + 1023) / 1024, 1024>>>();
    transpose_w<<<1, 256>>>(W1l, W1r, W2l, W2r);

    // CSR build (reused by both layers)
    hist_kernel<<<EG, 256>>>(ei);
    scan1_kernel<<<NBLK, 1024>>>();
    scan2_kernel<<<1, 128>>>();
    scan3_kernel<<<NBLK, 1024>>>();
    fill_kernel<<<EG, 256>>>(ei);

    // fused layers
    sage_layer<0, 0><<<LG, 256>>>(x, b1, nullptr, nullptr, nullptr, nullptr);
    if (out_size >= NN * (D + 1)) {
        sage_layer<1, 1><<<LG, 256>>>(nullptr, b2, outp + NN, Wh, bh, outp);
    } else {
        sage_layer<1, 0><<<LG, 256>>>(nullptr, b2, nullptr, Wh, bh, outp);
    }
}